// round 9
// baseline (speedup 1.0000x reference)
#include <cuda_runtime.h>
#include <math.h>
#include <stdint.h>

// ContrastiveLoss fused via warp-level FP8(e4m3) mma.sync (m16n8k32).
// 4 independent 4-warp groups per 512-thread CTA, each a self-paced
// load/MMA/exp-reduce pipeline over 128x64 tiles (named barriers only).
// xx-symmetric triangle at 64-col granularity; A tile resident per strip.
// Inputs: x [M,D] f32, track_idxs [M] i32, y [n,Q,D] f32. Output: scalar f32.

#define MAX_M  8192
#define DK     128
#define TILE   128
#define ASTRB  144            // padded row stride in bytes
#define NPCTA  148

// per-group smem layout (bytes), group block size GSZ
#define GA     0              // A tile 128 x 144
#define GB0    18432          // B buf0 64 x 144
#define GB1    27648          // B buf1
#define GTR    36864          // 128 row labels
#define GTC0   37376          // 64 col labels buf0
#define GTC1   37632          // 64 col labels buf1
#define GRRS   37888          // 128 f32 row sums
#define GRSS   38400          // 128 f32 same-track sums
#define GCCS   38912          // 64 f32 col sums
#define GSZ    39168
#define SM_TOTAL (4 * GSZ)    // 156672

__device__ uint8_t g_xa[(size_t)MAX_M * DK];       // x * log2(e)/T, e4m3 (A)
__device__ uint8_t g_x8[(size_t)MAX_M * DK];       // x, e4m3 (B, xx)
__device__ uint8_t g_y8[(size_t)MAX_M * DK / 2];   // y, e4m3 (B, xy)
__device__ double g_A[MAX_M];
__device__ double g_P[MAX_M];
__device__ double g_RT[MAX_M];
__device__ double g_G[MAX_M];
__device__ double g_DS[MAX_M];
__device__ int    g_n = 0;

__device__ __forceinline__ uint32_t smem_u32(const void* p) {
    uint32_t a;
    asm("{ .reg .u64 t; cvta.to.shared.u64 t, %1; cvt.u32.u64 %0, t; }" : "=r"(a) : "l"(p));
    return a;
}
__device__ __forceinline__ float ex2f(float x) {
    float r; asm("ex2.approx.f32 %0, %1;" : "=f"(r) : "f"(x)); return r;
}
__device__ __forceinline__ void ldmx4(uint32_t* r, uint32_t addr) {
    asm volatile("ldmatrix.sync.aligned.m8n8.x4.shared.b16 {%0,%1,%2,%3}, [%4];"
                 : "=r"(r[0]), "=r"(r[1]), "=r"(r[2]), "=r"(r[3]) : "r"(addr));
}
__device__ __forceinline__ void mma16832(float* d, const uint32_t* a, uint32_t b0, uint32_t b1) {
    asm volatile("mma.sync.aligned.m16n8k32.row.col.f32.e4m3.e4m3.f32 "
                 "{%0,%1,%2,%3}, {%4,%5,%6,%7}, {%8,%9}, {%0,%1,%2,%3};"
                 : "+f"(d[0]), "+f"(d[1]), "+f"(d[2]), "+f"(d[3])
                 : "r"(a[0]), "r"(a[1]), "r"(a[2]), "r"(a[3]), "r"(b0), "r"(b1));
}
__device__ __forceinline__ void cpasync16(uint32_t saddr, const void* gptr) {
    asm volatile("cp.async.cg.shared.global [%0], [%1], 16;" :: "r"(saddr), "l"(gptr));
}
__device__ __forceinline__ uint32_t pack_e4m3_4(float a, float b, float c, float d) {
    uint16_t lo, hi;
    asm("cvt.rn.satfinite.e4m3x2.f32 %0, %1, %2;" : "=h"(lo) : "f"(b), "f"(a));
    asm("cvt.rn.satfinite.e4m3x2.f32 %0, %1, %2;" : "=h"(hi) : "f"(d), "f"(c));
    return (uint32_t)lo | ((uint32_t)hi << 16);
}

// ---------------------------------------------------------------------------
__global__ void k_prep(const float* __restrict__ x, const float* __restrict__ y,
                       const int* __restrict__ trk, int M, int nQ) {
    const float S = 1.4426950408889634f / 0.3f;   // log2(e)/TEMP
    int t = blockIdx.x * blockDim.x + threadIdx.x;
    int nx4 = M * DK / 4;
    int ny4 = nQ * DK / 4;
    if (t < nx4) {
        float4 v = *reinterpret_cast<const float4*>(x + t * 4);
        *reinterpret_cast<uint32_t*>(g_xa + t * 4) =
            pack_e4m3_4(v.x * S, v.y * S, v.z * S, v.w * S);
        *reinterpret_cast<uint32_t*>(g_x8 + t * 4) = pack_e4m3_4(v.x, v.y, v.z, v.w);
    } else if (t < nx4 + ny4) {
        int i = t - nx4;
        float4 v = *reinterpret_cast<const float4*>(y + i * 4);
        *reinterpret_cast<uint32_t*>(g_y8 + i * 4) = pack_e4m3_4(v.x, v.y, v.z, v.w);
    }
    if (t < MAX_M) { g_A[t] = 0; g_P[t] = 0; g_RT[t] = 0; g_G[t] = 0; g_DS[t] = 0; }
    if (t < M) atomicMax(&g_n, trk[t] + 1);
}

// ---------------------------------------------------------------------------
// strip-major tile unranking. Strip r (row-block of 128): xx col-blocks
// (64-wide) c = 2r .. 2*nXX-1 (first two are diag-mode), then nYc xy blocks.
// cum(r) = r*(C1 - r) with C1 = 2*nXX + nYc + 1.
__device__ __forceinline__ void decode_t(int t, int C1, int nXX, int& r, int& u) {
    float disc = (float)C1 * (float)C1 - 4.f * (float)t;
    int rr = (int)(((float)C1 - sqrtf(disc)) * 0.5f);
    if (rr < 0) rr = 0;
    if (rr > nXX - 1) rr = nXX - 1;
    while (rr + 1 <= nXX - 1 && (rr + 1) * (C1 - (rr + 1)) <= t) rr++;
    while (rr > 0 && rr * (C1 - rr) > t) rr--;
    r = rr;
    u = t - rr * (C1 - rr);
}

__global__ void __launch_bounds__(512, 1)
k_gemm(const int* __restrict__ trk, int M, int nQ) {
    extern __shared__ char smem[];
    int tid = threadIdx.x;
    int ltid = tid & 127;
    int grp = tid >> 7;
    char* gs = smem + grp * GSZ;
    uint32_t gb = smem_u32(gs);
    int lane = tid & 31;
    int wg = (tid >> 5) & 3;
    int n = g_n;

    int nXX = M / TILE;           // 64 row-blocks
    int nYc = nQ / 64;            // xy col-blocks
    int C1 = 2 * nXX + nYc + 1;
    int totTiles = nXX * (C1 - nXX);
    int nGroups = gridDim.x * 4;
    int gid = blockIdx.x * 4 + grp;
    int start = (int)(((long long)gid * totTiles) / nGroups);
    int end   = (int)(((long long)(gid + 1) * totTiles) / nGroups);

    int* trS = (int*)(gs + GTR);
    float* rowRS = (float*)(gs + GRRS);
    float* rowSS = (float*)(gs + GRSS);
    float* colCS = (float*)(gs + GCCS);

    rowRS[ltid] = 0.f; rowSS[ltid] = 0.f;
    if (ltid < 64) colCS[ltid] = 0.f;

    int m0 = (wg >> 1) * 64;
    int n0 = (wg & 1) * 32;
    int lrow = lane & 15;
    int lhalf = (lane >> 4) * 16;
    int q = lane >> 2, t4 = lane & 3;

    uint32_t aAddr[4];
#pragma unroll
    for (int mi = 0; mi < 4; mi++)
        aAddr[mi] = gb + GA + (m0 + mi * 16 + lrow) * ASTRB + lhalf;
    uint32_t bOff[2];
#pragma unroll
    for (int g2 = 0; g2 < 2; g2++)
        bOff[g2] = (n0 + g2 * 16 + lrow) * ASTRB + lhalf;

#define GBAR() asm volatile("bar.sync %0, 128;" :: "r"(grp + 1) : "memory")

    if (start >= end) return;

    // ---- helpers as macros over locals ----
#define LOAD_A(RR) do {                                                        \
        const uint8_t* asrc_ = g_xa + (size_t)(RR) * TILE * DK;                \
        _Pragma("unroll")                                                      \
        for (int it = 0; it < 8; it++) {                                       \
            int c_ = ltid + it * 128;                                          \
            int row_ = c_ >> 3, col_ = (c_ & 7) << 4;                          \
            cpasync16(gb + GA + row_ * ASTRB + col_, asrc_ + row_ * DK + col_);\
        }                                                                      \
        if (ltid < 32)                                                         \
            cpasync16(gb + GTR + ltid * 16, trk + (RR) * TILE + ltid * 4);     \
    } while (0)

#define LOAD_B(RR, UU, BUF) do {                                               \
        int nxx_ = 2 * nXX - 2 * (RR);                                         \
        uint32_t dstB_ = gb + ((BUF) ? GB1 : GB0);                             \
        if ((UU) < nxx_) {                                                     \
            int cblk_ = 2 * (RR) + (UU);                                       \
            const uint8_t* bsrc_ = g_x8 + (size_t)cblk_ * 64 * DK;             \
            _Pragma("unroll")                                                  \
            for (int it = 0; it < 4; it++) {                                   \
                int c_ = ltid + it * 128;                                      \
                int row_ = c_ >> 3, col_ = (c_ & 7) << 4;                      \
                cpasync16(dstB_ + row_ * ASTRB + col_, bsrc_ + row_ * DK + col_);\
            }                                                                  \
            if (ltid < 16)                                                     \
                cpasync16(gb + GTC0 + (BUF) * 256 + ltid * 16,                 \
                          trk + cblk_ * 64 + ltid * 4);                        \
        } else {                                                               \
            int j_ = (UU) - nxx_;                                              \
            const uint8_t* bsrc_ = g_y8 + (size_t)j_ * 64 * DK;                \
            _Pragma("unroll")                                                  \
            for (int it = 0; it < 4; it++) {                                   \
                int c_ = ltid + it * 128;                                      \
                int row_ = c_ >> 3, col_ = (c_ & 7) << 4;                      \
                cpasync16(dstB_ + row_ * ASTRB + col_, bsrc_ + row_ * DK + col_);\
            }                                                                  \
            if (ltid < 64)                                                     \
                ((int*)(gs + GTC0 + (BUF) * 256))[ltid] = (j_ * 64 + ltid) % n;\
        }                                                                      \
    } while (0)

    // ---- prologue ----
    int rc, uc;
    decode_t(start, C1, nXX, rc, uc);
    LOAD_A(rc);
    LOAD_B(rc, uc, 0);
    asm volatile("cp.async.commit_group;" ::: "memory");

    int buf = 0;
    for (int t = start; t < end; t++) {
        asm volatile("cp.async.wait_group 0;" ::: "memory");
        GBAR();

        // prefetch next tile's B (A deferred if strip changes)
        bool haveNext = (t + 1 < end);
        int rn = rc, un = 0;
        if (haveNext) {
            decode_t(t + 1, C1, nXX, rn, un);
            LOAD_B(rn, un, buf ^ 1);
        }
        asm volatile("cp.async.commit_group;" ::: "memory");

        // current tile flags
        int nxx_c = 2 * nXX - 2 * rc;
        bool isXY = (uc >= nxx_c);
        bool isDiag = (!isXY) && (uc < 2);
        bool isOff = (!isXY) && (uc >= 2);
        int grow0 = rc * TILE;
        int gcol0 = (2 * rc + uc) * 64;   // valid for xx only
        const int* tcC = (const int*)(gs + GTC0 + buf * 256);
        uint32_t bBase = gb + (buf ? GB1 : GB0);

        // ---- MMA ----
        float acc[4][4][4];
#pragma unroll
        for (int mi = 0; mi < 4; mi++)
#pragma unroll
            for (int ni = 0; ni < 4; ni++)
#pragma unroll
                for (int e = 0; e < 4; e++) acc[mi][ni][e] = 0.f;

#pragma unroll
        for (int ks = 0; ks < 4; ks++) {
            uint32_t a[4][4], b[2][4];
#pragma unroll
            for (int mi = 0; mi < 4; mi++) ldmx4(a[mi], aAddr[mi] + ks * 32);
#pragma unroll
            for (int g2 = 0; g2 < 2; g2++) ldmx4(b[g2], bBase + bOff[g2] + ks * 32);
#pragma unroll
            for (int mi = 0; mi < 4; mi++) {
                mma16832(acc[mi][0], a[mi], b[0][0], b[0][2]);
                mma16832(acc[mi][1], a[mi], b[0][1], b[0][3]);
                mma16832(acc[mi][2], a[mi], b[1][0], b[1][2]);
                mma16832(acc[mi][3], a[mi], b[1][1], b[1][3]);
            }
        }

        // ---- epilogue: exp + reductions (overlaps in-flight cp.async) ----
        int tcJ[8];
#pragma unroll
        for (int j = 0; j < 8; j++) {
            int ni = j >> 1, p = j & 1;
            tcJ[j] = tcC[n0 + ni * 8 + t4 * 2 + p];
        }
        float cs[4][2] = {{0.f,0.f},{0.f,0.f},{0.f,0.f},{0.f,0.f}};
#pragma unroll
        for (int mi = 0; mi < 4; mi++) {
#pragma unroll
            for (int h = 0; h < 2; h++) {
                int rloc = m0 + mi * 16 + q + h * 8;
                int tr = trS[rloc];
                int grow = grow0 + rloc;
                float r_s = 0.f, s_s = 0.f;
#pragma unroll
                for (int ni = 0; ni < 4; ni++) {
#pragma unroll
                    for (int p = 0; p < 2; p++) {
                        float e = ex2f(acc[mi][ni][h * 2 + p]);
                        r_s += e;
                        if (tcJ[ni * 2 + p] == tr) s_s += e;
                        if (isDiag && (gcol0 + n0 + ni * 8 + t4 * 2 + p == grow))
                            atomicAdd(&g_DS[tr], (double)e);
                        if (isOff) cs[ni][p] += e;
                    }
                }
                r_s += __shfl_xor_sync(0xffffffffu, r_s, 1);
                r_s += __shfl_xor_sync(0xffffffffu, r_s, 2);
                s_s += __shfl_xor_sync(0xffffffffu, s_s, 1);
                s_s += __shfl_xor_sync(0xffffffffu, s_s, 2);
                if (t4 == 0) {
                    atomicAdd(&rowRS[rloc], r_s);
                    atomicAdd(&rowSS[rloc], s_s);
                }
            }
        }
        if (isOff) {
#pragma unroll
            for (int ni = 0; ni < 4; ni++) {
#pragma unroll
                for (int p = 0; p < 2; p++) {
                    float v = cs[ni][p];
                    v += __shfl_xor_sync(0xffffffffu, v, 4);
                    v += __shfl_xor_sync(0xffffffffu, v, 8);
                    v += __shfl_xor_sync(0xffffffffu, v, 16);
                    if (q == 0)
                        atomicAdd(&colCS[n0 + ni * 8 + t4 * 2 + p], v);
                }
            }
        }
        GBAR();

        // ---- flush + rezero ----
        {
            int tr = trS[ltid];
            float rv = rowRS[ltid], sv = rowSS[ltid];
            if (isXY) {
                atomicAdd(&g_A[tr], (double)rv);
                atomicAdd(&g_P[tr], (double)sv);
            } else if (isDiag) {
                atomicAdd(&g_RT[tr], (double)rv);
                atomicAdd(&g_G[tr], (double)sv);
            } else {
                atomicAdd(&g_RT[tr], (double)rv);
                atomicAdd(&g_G[tr], 2.0 * (double)sv);
                if (ltid < 64) {
                    atomicAdd(&g_RT[tcC[ltid]], (double)colCS[ltid]);
                    colCS[ltid] = 0.f;
                }
            }
            rowRS[ltid] = 0.f; rowSS[ltid] = 0.f;
        }

        // strip change: reload A + row labels (deferred; rare)
        if (haveNext && rn != rc) {
            GBAR();                 // everyone done reading trS / A
            LOAD_A(rn);
            asm volatile("cp.async.commit_group;" ::: "memory");
        }
        rc = rn; uc = un;
        buf ^= 1;
    }
#undef GBAR
#undef LOAD_A
#undef LOAD_B
}

// ---------------------------------------------------------------------------
__global__ void k_loss(float* out, int nQ) {
    __shared__ double warpsum[16];
    int n = g_n;
    int Q = nQ / n;
    double local = 0.0;
    for (int i = threadIdx.x; i < n; i += blockDim.x) {
        double num = g_P[i] + 0.5 * (g_G[i] - g_DS[i]);
        double den = (g_A[i] - g_P[i]) + (g_RT[i] - g_G[i]);
        local += (double)logf((float)((num + den) / num));
    }
#pragma unroll
    for (int o = 16; o >= 1; o >>= 1)
        local += __shfl_xor_sync(0xffffffffu, local, o);
    int lane = threadIdx.x & 31, wi = threadIdx.x >> 5;
    if (lane == 0) warpsum[wi] = local;
    __syncthreads();
    if (threadIdx.x == 0) {
        double t = 0.0;
        for (int i = 0; i < (int)(blockDim.x >> 5); i++) t += warpsum[i];
        out[0] = (float)(t / (double)n / (double)Q);
    }
}

// ---------------------------------------------------------------------------
extern "C" void kernel_launch(void* const* d_in, const int* in_sizes, int n_in,
                              void* d_out, int out_size) {
    const float* x   = (const float*)d_in[0];
    const int*   trk = (const int*)d_in[1];
    const float* y   = (const float*)d_in[2];
    float* out = (float*)d_out;

    int M  = in_sizes[1];
    int D  = in_sizes[0] / M;
    int nQ = in_sizes[2] / D;

    cudaFuncSetAttribute(k_gemm, cudaFuncAttributeMaxDynamicSharedMemorySize, SM_TOTAL);

    int prepThreads = (M * D + nQ * D) / 4;
    if (prepThreads < MAX_M) prepThreads = MAX_M;
    k_prep<<<(prepThreads + 255) / 256, 256>>>(x, y, trk, M, nQ);

    k_gemm<<<NPCTA, 512, SM_TOTAL>>>(trk, M, nQ);

    k_loss<<<1, 512>>>(out, nQ);
}

// round 10
// speedup vs baseline: 1.2048x; 1.2048x over previous
#include <cuda_runtime.h>
#include <math.h>
#include <stdint.h>

// ContrastiveLoss fused via warp-level FP8(e4m3) mma.sync (m16n8k32).
// Strip-major persistent CTAs: A tile + row labels resident per strip
// (double-buffered), B double-buffered, row sums staged in per-warp smem
// slices and flushed only at strip/mode boundaries. One barrier per tile.
// Inputs: x [M,D] f32, track_idxs [M] i32, y [n,Q,D] f32. Output: scalar f32.

#define MAX_M  8192
#define DK     128
#define TILE   128
#define ASTRB  144            // padded row stride in bytes
#define NPCTA  296            // 2 per SM

// smem layout (bytes)
#define GA0    0              // A buf0 128x144
#define GA1    18432          // A buf1
#define GB0    36864          // B buf0
#define GB1    55296          // B buf1
#define GTRS   73728          // 2 x 512 row labels (paired with A bufs)
#define GTCS   74752          // 2 x 512 col labels (paired with B bufs)
#define GRS    75776          // 4 slices x 128 f32 row sums
#define GSS    77824          // 4 slices x 128 f32 same-track sums
#define SM_TOTAL 79872

__device__ uint8_t g_xa[(size_t)MAX_M * DK];       // x * log2(e)/T, e4m3 (A)
__device__ uint8_t g_x8[(size_t)MAX_M * DK];       // x, e4m3 (B, xx)
__device__ uint8_t g_y8[(size_t)MAX_M * DK / 2];   // y, e4m3 (B, xy)
__device__ double g_A[MAX_M];
__device__ double g_P[MAX_M];
__device__ double g_RT[MAX_M];
__device__ double g_G[MAX_M];
__device__ double g_DS[MAX_M];
__device__ int    g_n = 0;

__device__ __forceinline__ uint32_t smem_u32(const void* p) {
    uint32_t a;
    asm("{ .reg .u64 t; cvta.to.shared.u64 t, %1; cvt.u32.u64 %0, t; }" : "=r"(a) : "l"(p));
    return a;
}
__device__ __forceinline__ float ex2f(float x) {
    float r; asm("ex2.approx.f32 %0, %1;" : "=f"(r) : "f"(x)); return r;
}
__device__ __forceinline__ void ldmx4(uint32_t* r, uint32_t addr) {
    asm volatile("ldmatrix.sync.aligned.m8n8.x4.shared.b16 {%0,%1,%2,%3}, [%4];"
                 : "=r"(r[0]), "=r"(r[1]), "=r"(r[2]), "=r"(r[3]) : "r"(addr));
}
__device__ __forceinline__ void mma16832(float* d, const uint32_t* a, uint32_t b0, uint32_t b1) {
    asm volatile("mma.sync.aligned.m16n8k32.row.col.f32.e4m3.e4m3.f32 "
                 "{%0,%1,%2,%3}, {%4,%5,%6,%7}, {%8,%9}, {%0,%1,%2,%3};"
                 : "+f"(d[0]), "+f"(d[1]), "+f"(d[2]), "+f"(d[3])
                 : "r"(a[0]), "r"(a[1]), "r"(a[2]), "r"(a[3]), "r"(b0), "r"(b1));
}
__device__ __forceinline__ void cpasync16(uint32_t saddr, const void* gptr) {
    asm volatile("cp.async.cg.shared.global [%0], [%1], 16;" :: "r"(saddr), "l"(gptr));
}
__device__ __forceinline__ uint32_t pack_e4m3_4(float a, float b, float c, float d) {
    uint16_t lo, hi;
    asm("cvt.rn.satfinite.e4m3x2.f32 %0, %1, %2;" : "=h"(lo) : "f"(b), "f"(a));
    asm("cvt.rn.satfinite.e4m3x2.f32 %0, %1, %2;" : "=h"(hi) : "f"(d), "f"(c));
    return (uint32_t)lo | ((uint32_t)hi << 16);
}

// ---------------------------------------------------------------------------
__global__ void k_prep(const float* __restrict__ x, const float* __restrict__ y,
                       const int* __restrict__ trk, int M, int nQ) {
    const float S = 1.4426950408889634f / 0.3f;   // log2(e)/TEMP
    int t = blockIdx.x * blockDim.x + threadIdx.x;
    int nx4 = M * DK / 4;
    int ny4 = nQ * DK / 4;
    if (t < nx4) {
        float4 v = *reinterpret_cast<const float4*>(x + t * 4);
        *reinterpret_cast<uint32_t*>(g_xa + t * 4) =
            pack_e4m3_4(v.x * S, v.y * S, v.z * S, v.w * S);
        *reinterpret_cast<uint32_t*>(g_x8 + t * 4) = pack_e4m3_4(v.x, v.y, v.z, v.w);
    } else if (t < nx4 + ny4) {
        int i = t - nx4;
        float4 v = *reinterpret_cast<const float4*>(y + i * 4);
        *reinterpret_cast<uint32_t*>(g_y8 + i * 4) = pack_e4m3_4(v.x, v.y, v.z, v.w);
    }
    if (t < MAX_M) { g_A[t] = 0; g_P[t] = 0; g_RT[t] = 0; g_G[t] = 0; g_DS[t] = 0; }
    if (t < M) atomicMax(&g_n, trk[t] + 1);
}

// ---------------------------------------------------------------------------
// strip-major unranking. Strip r: xx col-blocks c = r..nXX-1 (u = c-r, u==0
// diag), then nYc xy blocks. count(r) = (nXX - r) + nYc.
// cum(r) = C*r - r(r-1)/2, C = nXX + nYc.
__device__ __forceinline__ void decode_t(int t, int C, int nXX, int& r, int& u) {
    float b = 2.f * C + 1.f;
    float disc = b * b - 8.f * (float)t;
    int rr = (int)((b - sqrtf(disc)) * 0.5f);
    if (rr < 0) rr = 0;
    if (rr > nXX - 1) rr = nXX - 1;
    while (rr + 1 <= nXX - 1 && (rr + 1) * C - ((rr + 1) * rr) / 2 <= t) rr++;
    while (rr > 0 && rr * C - (rr * (rr - 1)) / 2 > t) rr--;
    r = rr;
    u = t - (rr * C - (rr * (rr - 1)) / 2);
}

__global__ void __launch_bounds__(256, 2)
k_gemm(const int* __restrict__ trk, int M, int nQ) {
    extern __shared__ char smem[];
    uint32_t gb = smem_u32(smem);
    int tid = threadIdx.x;
    int w = tid >> 5, lane = tid & 31;
    int n = g_n;

    int nXX = M / TILE;           // 64
    int nYc = nQ / TILE;          // 32
    int C = nXX + nYc;            // 96
    int totTiles = nXX * C - (nXX * (nXX - 1)) / 2;   // 4128
    int start = (int)(((long long)blockIdx.x * totTiles) / gridDim.x);
    int end   = (int)(((long long)(blockIdx.x + 1) * totTiles) / gridDim.x);

    float* rsS = (float*)(smem + GRS);   // [4][128]
    float* ssS = (float*)(smem + GSS);   // [4][128]
    if (tid < 128) {
#pragma unroll
        for (int s = 0; s < 4; s++) { rsS[s * 128 + tid] = 0.f; ssS[s * 128 + tid] = 0.f; }
    }

    int m0 = (w >> 2) * 64;
    int n0 = (w & 3) * 32;
    int slice = w & 3;
    int lrow = lane & 15;
    int lhalf = (lane >> 4) * 16;
    int q = lane >> 2, t4 = lane & 3;

    if (start >= end) return;

#define LOAD_A(RR, AB) do {                                                     \
        uint32_t dstA_ = gb + ((AB) ? GA1 : GA0);                               \
        const uint8_t* asrc_ = g_xa + (size_t)(RR) * TILE * DK;                 \
        _Pragma("unroll")                                                       \
        for (int it = 0; it < 4; it++) {                                        \
            int c_ = tid + it * 256;                                            \
            int row_ = c_ >> 3, col_ = (c_ & 7) << 4;                           \
            cpasync16(dstA_ + row_ * ASTRB + col_, asrc_ + row_ * DK + col_);   \
        }                                                                       \
        if (tid < 32)                                                           \
            cpasync16(gb + GTRS + (AB) * 512 + tid * 16,                        \
                      trk + (RR) * TILE + tid * 4);                             \
    } while (0)

#define LOAD_B(RR, UU, BB) do {                                                 \
        uint32_t dstB_ = gb + ((BB) ? GB1 : GB0);                               \
        int nxx_ = nXX - (RR);                                                  \
        if ((UU) < nxx_) {                                                      \
            int cblk_ = (RR) + (UU);                                            \
            const uint8_t* bsrc_ = g_x8 + (size_t)cblk_ * TILE * DK;            \
            _Pragma("unroll")                                                   \
            for (int it = 0; it < 4; it++) {                                    \
                int c_ = tid + it * 256;                                        \
                int row_ = c_ >> 3, col_ = (c_ & 7) << 4;                       \
                cpasync16(dstB_ + row_ * ASTRB + col_, bsrc_ + row_ * DK + col_);\
            }                                                                   \
            if (tid < 32)                                                       \
                cpasync16(gb + GTCS + (BB) * 512 + tid * 16,                    \
                          trk + cblk_ * TILE + tid * 4);                        \
        } else {                                                                \
            int j_ = (UU) - nxx_;                                               \
            const uint8_t* bsrc_ = g_y8 + (size_t)j_ * TILE * DK;               \
            _Pragma("unroll")                                                   \
            for (int it = 0; it < 4; it++) {                                    \
                int c_ = tid + it * 256;                                        \
                int row_ = c_ >> 3, col_ = (c_ & 7) << 4;                       \
                cpasync16(dstB_ + row_ * ASTRB + col_, bsrc_ + row_ * DK + col_);\
            }                                                                   \
            if (tid < 128)                                                      \
                ((int*)(smem + GTCS + (BB) * 512))[tid] = (j_ * TILE + tid) % n;\
        }                                                                       \
    } while (0)

    // ---- prologue ----
    int rc, uc;
    decode_t(start, C, nXX, rc, uc);
    int aBuf = 0, bBuf = 0;
    LOAD_A(rc, 0);
    LOAD_B(rc, uc, 0);
    asm volatile("cp.async.commit_group;" ::: "memory");

    for (int t = start; t < end; t++) {
        asm volatile("cp.async.wait_group 0;" ::: "memory");
        __syncthreads();

        // ---- prefetch tile t+1 ----
        bool haveNext = (t + 1 < end);
        int rn = rc, un = 0;
        bool aFlip = false;
        if (haveNext) {
            decode_t(t + 1, C, nXX, rn, un);
            LOAD_B(rn, un, bBuf ^ 1);
            if (rn != rc) { LOAD_A(rn, aBuf ^ 1); aFlip = true; }
        }
        asm volatile("cp.async.commit_group;" ::: "memory");

        // ---- current tile flags ----
        bool isXY = (uc >= nXX - rc);
        bool isDiag = (!isXY) && (uc == 0);
        bool isOff = (!isXY) && (uc > 0);
        const int* trC = (const int*)(smem + GTRS + aBuf * 512);
        const int* tcC = (const int*)(smem + GTCS + bBuf * 512);
        uint32_t aBase = gb + (aBuf ? GA1 : GA0);
        uint32_t bBase = gb + (bBuf ? GB1 : GB0);
        float gmult = isOff ? 2.f : 1.f;

        // ---- MMA ----
        uint32_t aAddr[4];
#pragma unroll
        for (int mi = 0; mi < 4; mi++)
            aAddr[mi] = aBase + (m0 + mi * 16 + lrow) * ASTRB + lhalf;
        uint32_t bAddr[2];
#pragma unroll
        for (int g2 = 0; g2 < 2; g2++)
            bAddr[g2] = bBase + (n0 + g2 * 16 + lrow) * ASTRB + lhalf;

        float acc[4][4][4];
#pragma unroll
        for (int mi = 0; mi < 4; mi++)
#pragma unroll
            for (int ni = 0; ni < 4; ni++)
#pragma unroll
                for (int e = 0; e < 4; e++) acc[mi][ni][e] = 0.f;

#pragma unroll
        for (int ks = 0; ks < 4; ks++) {
            uint32_t a[4][4], b[2][4];
#pragma unroll
            for (int mi = 0; mi < 4; mi++) ldmx4(a[mi], aAddr[mi] + ks * 32);
#pragma unroll
            for (int g2 = 0; g2 < 2; g2++) ldmx4(b[g2], bAddr[g2] + ks * 32);
#pragma unroll
            for (int mi = 0; mi < 4; mi++) {
                mma16832(acc[mi][0], a[mi], b[0][0], b[0][2]);
                mma16832(acc[mi][1], a[mi], b[0][1], b[0][3]);
                mma16832(acc[mi][2], a[mi], b[1][0], b[1][2]);
                mma16832(acc[mi][3], a[mi], b[1][1], b[1][3]);
            }
        }

        // ---- epilogue: exp + staged row sums, direct col sums ----
        int tcJ[8];
#pragma unroll
        for (int j = 0; j < 8; j++) {
            int ni = j >> 1, p = j & 1;
            tcJ[j] = tcC[n0 + ni * 8 + t4 * 2 + p];
        }
        float cs[4][2] = {{0.f,0.f},{0.f,0.f},{0.f,0.f},{0.f,0.f}};
#pragma unroll
        for (int mi = 0; mi < 4; mi++) {
#pragma unroll
            for (int h = 0; h < 2; h++) {
                int rloc = m0 + mi * 16 + q + h * 8;
                int tr = trC[rloc];
                float r_s = 0.f, s_s = 0.f;
#pragma unroll
                for (int ni = 0; ni < 4; ni++) {
#pragma unroll
                    for (int p = 0; p < 2; p++) {
                        float e = ex2f(acc[mi][ni][h * 2 + p]);
                        r_s += e;
                        if (tcJ[ni * 2 + p] == tr) s_s += e;
                        if (isDiag && (n0 + ni * 8 + t4 * 2 + p == rloc))
                            atomicAdd(&g_DS[tr], (double)e);
                        if (isOff) cs[ni][p] += e;
                    }
                }
                r_s += __shfl_xor_sync(0xffffffffu, r_s, 1);
                r_s += __shfl_xor_sync(0xffffffffu, r_s, 2);
                s_s += __shfl_xor_sync(0xffffffffu, s_s, 1);
                s_s += __shfl_xor_sync(0xffffffffu, s_s, 2);
                if (t4 == 0) {
                    rsS[slice * 128 + rloc] += r_s;
                    ssS[slice * 128 + rloc] += s_s * gmult;
                }
            }
        }
        if (isOff) {
#pragma unroll
            for (int ni = 0; ni < 4; ni++) {
#pragma unroll
                for (int p = 0; p < 2; p++) {
                    float v = cs[ni][p];
                    v += __shfl_xor_sync(0xffffffffu, v, 4);
                    v += __shfl_xor_sync(0xffffffffu, v, 8);
                    v += __shfl_xor_sync(0xffffffffu, v, 16);
                    if (q == 0)
                        atomicAdd(&g_RT[tcJ[ni * 2 + p]], (double)v);
                }
            }
        }

        // ---- flush on strip/mode boundary ----
        bool nIsXY = haveNext && (un >= nXX - rn);
        bool keep = haveNext && (rn == rc) && (nIsXY == isXY);
        if (!keep) {
            __syncthreads();
            if (tid < 128) {
                float rv = rsS[tid] + rsS[128 + tid] + rsS[256 + tid] + rsS[384 + tid];
                float sv = ssS[tid] + ssS[128 + tid] + ssS[256 + tid] + ssS[384 + tid];
                int tr = trC[tid];
                if (isXY) {
                    atomicAdd(&g_A[tr], (double)rv);
                    atomicAdd(&g_P[tr], (double)sv);
                } else {
                    atomicAdd(&g_RT[tr], (double)rv);
                    atomicAdd(&g_G[tr], (double)sv);
                }
#pragma unroll
                for (int s = 0; s < 4; s++) {
                    rsS[s * 128 + tid] = 0.f;
                    ssS[s * 128 + tid] = 0.f;
                }
            }
        }

        rc = rn; uc = un;
        bBuf ^= 1;
        if (aFlip) aBuf ^= 1;
    }
#undef LOAD_A
#undef LOAD_B
}

// ---------------------------------------------------------------------------
__global__ void k_loss(float* out, int nQ) {
    __shared__ double warpsum[16];
    int n = g_n;
    int Q = nQ / n;
    double local = 0.0;
    for (int i = threadIdx.x; i < n; i += blockDim.x) {
        double num = g_P[i] + 0.5 * (g_G[i] - g_DS[i]);
        double den = (g_A[i] - g_P[i]) + (g_RT[i] - g_G[i]);
        local += (double)logf((float)((num + den) / num));
    }
#pragma unroll
    for (int o = 16; o >= 1; o >>= 1)
        local += __shfl_xor_sync(0xffffffffu, local, o);
    int lane = threadIdx.x & 31, wi = threadIdx.x >> 5;
    if (lane == 0) warpsum[wi] = local;
    __syncthreads();
    if (threadIdx.x == 0) {
        double t = 0.0;
        for (int i = 0; i < (int)(blockDim.x >> 5); i++) t += warpsum[i];
        out[0] = (float)(t / (double)n / (double)Q);
    }
}

// ---------------------------------------------------------------------------
extern "C" void kernel_launch(void* const* d_in, const int* in_sizes, int n_in,
                              void* d_out, int out_size) {
    const float* x   = (const float*)d_in[0];
    const int*   trk = (const int*)d_in[1];
    const float* y   = (const float*)d_in[2];
    float* out = (float*)d_out;

    int M  = in_sizes[1];
    int D  = in_sizes[0] / M;
    int nQ = in_sizes[2] / D;

    cudaFuncSetAttribute(k_gemm, cudaFuncAttributeMaxDynamicSharedMemorySize, SM_TOTAL);

    int prepThreads = (M * D + nQ * D) / 4;
    if (prepThreads < MAX_M) prepThreads = MAX_M;
    k_prep<<<(prepThreads + 255) / 256, 256>>>(x, y, trk, M, nQ);

    k_gemm<<<NPCTA, 256, SM_TOTAL>>>(trk, M, nQ);

    k_loss<<<1, 512>>>(out, nQ);
}

// round 11
// speedup vs baseline: 1.3571x; 1.1265x over previous
#include <cuda_runtime.h>
#include <math.h>
#include <stdint.h>

// ContrastiveLoss fused via warp-level FP8(e4m3) mma.sync (m16n8k32).
// Strip-major persistent CTAs, A resident per strip (double-buffered),
// B double-buffered, smem-staged row sums flushed at strip/mode boundaries,
// incremental tile tracking, mode-specialized epilogues.
// Inputs: x [M,D] f32, track_idxs [M] i32, y [n,Q,D] f32. Output: scalar f32.

#define MAX_M  8192
#define DK     128
#define TILE   128
#define ASTRB  144            // padded row stride in bytes
#define NPCTA  296            // 2 per SM

// smem layout (bytes)
#define GA0    0              // A buf0 128x144
#define GA1    18432          // A buf1
#define GB0    36864          // B buf0
#define GB1    55296          // B buf1
#define GTRS   73728          // 2 x 512 row labels (paired with A bufs)
#define GTCS   74752          // 2 x 512 col labels (paired with B bufs)
#define GRS    75776          // 4 slices x 128 f32 row sums
#define GSS    77824          // 4 slices x 128 f32 same-track sums
#define SM_TOTAL 79872

__device__ uint8_t g_xa[(size_t)MAX_M * DK];       // x * log2(e)/T, e4m3 (A)
__device__ uint8_t g_x8[(size_t)MAX_M * DK];       // x, e4m3 (B, xx)
__device__ uint8_t g_y8[(size_t)MAX_M * DK / 2];   // y, e4m3 (B, xy)
__device__ double g_A[MAX_M];
__device__ double g_P[MAX_M];
__device__ double g_RT[MAX_M];
__device__ double g_G[MAX_M];
__device__ double g_DS[MAX_M];
__device__ int    g_n = 0;

__device__ __forceinline__ uint32_t smem_u32(const void* p) {
    uint32_t a;
    asm("{ .reg .u64 t; cvta.to.shared.u64 t, %1; cvt.u32.u64 %0, t; }" : "=r"(a) : "l"(p));
    return a;
}
__device__ __forceinline__ float ex2f(float x) {
    float r; asm("ex2.approx.f32 %0, %1;" : "=f"(r) : "f"(x)); return r;
}
__device__ __forceinline__ void ldmx4(uint32_t* r, uint32_t addr) {
    asm volatile("ldmatrix.sync.aligned.m8n8.x4.shared.b16 {%0,%1,%2,%3}, [%4];"
                 : "=r"(r[0]), "=r"(r[1]), "=r"(r[2]), "=r"(r[3]) : "r"(addr));
}
__device__ __forceinline__ void mma16832(float* d, const uint32_t* a, uint32_t b0, uint32_t b1) {
    asm volatile("mma.sync.aligned.m16n8k32.row.col.f32.e4m3.e4m3.f32 "
                 "{%0,%1,%2,%3}, {%4,%5,%6,%7}, {%8,%9}, {%0,%1,%2,%3};"
                 : "+f"(d[0]), "+f"(d[1]), "+f"(d[2]), "+f"(d[3])
                 : "r"(a[0]), "r"(a[1]), "r"(a[2]), "r"(a[3]), "r"(b0), "r"(b1));
}
__device__ __forceinline__ void cpasync16(uint32_t saddr, const void* gptr) {
    asm volatile("cp.async.cg.shared.global [%0], [%1], 16;" :: "r"(saddr), "l"(gptr));
}
__device__ __forceinline__ uint32_t pack_e4m3_4(float a, float b, float c, float d) {
    uint16_t lo, hi;
    asm("cvt.rn.satfinite.e4m3x2.f32 %0, %1, %2;" : "=h"(lo) : "f"(b), "f"(a));
    asm("cvt.rn.satfinite.e4m3x2.f32 %0, %1, %2;" : "=h"(hi) : "f"(d), "f"(c));
    return (uint32_t)lo | ((uint32_t)hi << 16);
}

// ---------------------------------------------------------------------------
__global__ void k_prep(const float* __restrict__ x, const float* __restrict__ y,
                       const int* __restrict__ trk, int M, int nQ) {
    const float S = 1.4426950408889634f / 0.3f;   // log2(e)/TEMP
    int t0 = blockIdx.x * blockDim.x + threadIdx.x;
    int nx4 = M * DK / 4;
    int ny4 = nQ * DK / 4;
    int tot = nx4 + ny4;
    int stride = gridDim.x * blockDim.x;
#pragma unroll 2
    for (int t = t0; t < tot; t += stride) {
        if (t < nx4) {
            float4 v = *reinterpret_cast<const float4*>(x + t * 4);
            *reinterpret_cast<uint32_t*>(g_xa + t * 4) =
                pack_e4m3_4(v.x * S, v.y * S, v.z * S, v.w * S);
            *reinterpret_cast<uint32_t*>(g_x8 + t * 4) = pack_e4m3_4(v.x, v.y, v.z, v.w);
        } else {
            int i = t - nx4;
            float4 v = *reinterpret_cast<const float4*>(y + i * 4);
            *reinterpret_cast<uint32_t*>(g_y8 + i * 4) = pack_e4m3_4(v.x, v.y, v.z, v.w);
        }
    }
    if (t0 < MAX_M) { g_A[t0] = 0; g_P[t0] = 0; g_RT[t0] = 0; g_G[t0] = 0; g_DS[t0] = 0; }
    if (t0 < M) atomicMax(&g_n, trk[t0] + 1);
}

// ---------------------------------------------------------------------------
// strip-major unranking (used once per CTA). Strip r: xx col-blocks u=0..
// nXX-r-1 (u==0 diag), then nYc xy blocks. cum(r) = C*r - r(r-1)/2.
__device__ __forceinline__ void decode_t(int t, int C, int nXX, int& r, int& u) {
    float b = 2.f * C + 1.f;
    float disc = b * b - 8.f * (float)t;
    int rr = (int)((b - sqrtf(disc)) * 0.5f);
    if (rr < 0) rr = 0;
    if (rr > nXX - 1) rr = nXX - 1;
    while (rr + 1 <= nXX - 1 && (rr + 1) * C - ((rr + 1) * rr) / 2 <= t) rr++;
    while (rr > 0 && rr * C - (rr * (rr - 1)) / 2 > t) rr--;
    r = rr;
    u = t - (rr * C - (rr * (rr - 1)) / 2);
}

__global__ void __launch_bounds__(256, 2)
k_gemm(const int* __restrict__ trk, int M, int nQ) {
    extern __shared__ char smem[];
    uint32_t gb = smem_u32(smem);
    int tid = threadIdx.x;
    int w = tid >> 5, lane = tid & 31;
    int n = g_n;

    int nXX = M / TILE;           // 64
    int nYc = nQ / TILE;          // 32
    int C = nXX + nYc;            // 96
    int totTiles = nXX * C - (nXX * (nXX - 1)) / 2;   // 4128
    int start = (int)(((long long)blockIdx.x * totTiles) / gridDim.x);
    int end   = (int)(((long long)(blockIdx.x + 1) * totTiles) / gridDim.x);

    float* rsS = (float*)(smem + GRS);   // [4][128]
    float* ssS = (float*)(smem + GSS);   // [4][128]
    if (tid < 128) {
#pragma unroll
        for (int s = 0; s < 4; s++) { rsS[s * 128 + tid] = 0.f; ssS[s * 128 + tid] = 0.f; }
    }

    int m0 = (w >> 2) * 64;
    int n0 = (w & 3) * 32;
    int slice = w & 3;
    int lrow = lane & 15;
    int lhalf = (lane >> 4) * 16;
    int q = lane >> 2, t4 = lane & 3;

    if (start >= end) return;

#define LOAD_A(RR, AB) do {                                                     \
        uint32_t dstA_ = gb + ((AB) ? GA1 : GA0);                               \
        const uint8_t* asrc_ = g_xa + (size_t)(RR) * TILE * DK;                 \
        _Pragma("unroll")                                                       \
        for (int it = 0; it < 4; it++) {                                        \
            int c_ = tid + it * 256;                                            \
            int row_ = c_ >> 3, col_ = (c_ & 7) << 4;                           \
            cpasync16(dstA_ + row_ * ASTRB + col_, asrc_ + row_ * DK + col_);   \
        }                                                                       \
        if (tid < 32)                                                           \
            cpasync16(gb + GTRS + (AB) * 512 + tid * 16,                        \
                      trk + (RR) * TILE + tid * 4);                             \
    } while (0)

#define LOAD_B(RR, UU, BB) do {                                                 \
        uint32_t dstB_ = gb + ((BB) ? GB1 : GB0);                               \
        int nxx_ = nXX - (RR);                                                  \
        if ((UU) < nxx_) {                                                      \
            int cblk_ = (RR) + (UU);                                            \
            const uint8_t* bsrc_ = g_x8 + (size_t)cblk_ * TILE * DK;            \
            _Pragma("unroll")                                                   \
            for (int it = 0; it < 4; it++) {                                    \
                int c_ = tid + it * 256;                                        \
                int row_ = c_ >> 3, col_ = (c_ & 7) << 4;                       \
                cpasync16(dstB_ + row_ * ASTRB + col_, bsrc_ + row_ * DK + col_);\
            }                                                                   \
            if (tid < 32)                                                       \
                cpasync16(gb + GTCS + (BB) * 512 + tid * 16,                    \
                          trk + cblk_ * TILE + tid * 4);                        \
        } else {                                                                \
            int j_ = (UU) - nxx_;                                               \
            const uint8_t* bsrc_ = g_y8 + (size_t)j_ * TILE * DK;               \
            _Pragma("unroll")                                                   \
            for (int it = 0; it < 4; it++) {                                    \
                int c_ = tid + it * 256;                                        \
                int row_ = c_ >> 3, col_ = (c_ & 7) << 4;                       \
                cpasync16(dstB_ + row_ * ASTRB + col_, bsrc_ + row_ * DK + col_);\
            }                                                                   \
            if (tid < 128)                                                      \
                ((int*)(smem + GTCS + (BB) * 512))[tid] = (j_ * TILE + tid) % n;\
        }                                                                       \
    } while (0)

    // ---- prologue ----
    int rc, uc;
    decode_t(start, C, nXX, rc, uc);
    int aBuf = 0, bBuf = 0;
    LOAD_A(rc, 0);
    LOAD_B(rc, uc, 0);
    asm volatile("cp.async.commit_group;" ::: "memory");

    for (int t = start; t < end; t++) {
        asm volatile("cp.async.wait_group 0;" ::: "memory");
        __syncthreads();

        // ---- next tile coords (incremental) ----
        bool haveNext = (t + 1 < end);
        int rn = rc, un = uc + 1;
        if (un == (nXX - rc) + nYc) { rn = rc + 1; un = 0; }
        bool aFlip = false;
        if (haveNext) {
            LOAD_B(rn, un, bBuf ^ 1);
            if (rn != rc) { LOAD_A(rn, aBuf ^ 1); aFlip = true; }
        }
        asm volatile("cp.async.commit_group;" ::: "memory");

        // ---- current tile flags ----
        bool isXY = (uc >= nXX - rc);
        bool isDiag = (uc == 0);
        const int* trC = (const int*)(smem + GTRS + aBuf * 512);
        const int* tcC = (const int*)(smem + GTCS + bBuf * 512);
        uint32_t aBase = gb + (aBuf ? GA1 : GA0);
        uint32_t bBase = gb + (bBuf ? GB1 : GB0);

        // ---- MMA ----
        uint32_t aAddr[4];
#pragma unroll
        for (int mi = 0; mi < 4; mi++)
            aAddr[mi] = aBase + (m0 + mi * 16 + lrow) * ASTRB + lhalf;
        uint32_t bAddr[2];
#pragma unroll
        for (int g2 = 0; g2 < 2; g2++)
            bAddr[g2] = bBase + (n0 + g2 * 16 + lrow) * ASTRB + lhalf;

        float acc[4][4][4];
#pragma unroll
        for (int mi = 0; mi < 4; mi++)
#pragma unroll
            for (int ni = 0; ni < 4; ni++)
#pragma unroll
                for (int e = 0; e < 4; e++) acc[mi][ni][e] = 0.f;

#pragma unroll
        for (int ks = 0; ks < 4; ks++) {
            uint32_t a[4][4], b[2][4];
#pragma unroll
            for (int mi = 0; mi < 4; mi++) ldmx4(a[mi], aAddr[mi] + ks * 32);
#pragma unroll
            for (int g2 = 0; g2 < 2; g2++) ldmx4(b[g2], bAddr[g2] + ks * 32);
#pragma unroll
            for (int mi = 0; mi < 4; mi++) {
                mma16832(acc[mi][0], a[mi], b[0][0], b[0][2]);
                mma16832(acc[mi][1], a[mi], b[0][1], b[0][3]);
                mma16832(acc[mi][2], a[mi], b[1][0], b[1][2]);
                mma16832(acc[mi][3], a[mi], b[1][1], b[1][3]);
            }
        }

        // ---- epilogue, specialized by tile mode ----
        int tcJ[8];
#pragma unroll
        for (int j = 0; j < 8; j++) {
            int ni = j >> 1, p = j & 1;
            tcJ[j] = tcC[n0 + ni * 8 + t4 * 2 + p];
        }

#define EPI_CORE(DODIAG, DOCS, GM) do {                                         \
        float cs[4][2] = {{0.f,0.f},{0.f,0.f},{0.f,0.f},{0.f,0.f}};             \
        _Pragma("unroll")                                                       \
        for (int mi = 0; mi < 4; mi++) {                                        \
            _Pragma("unroll")                                                   \
            for (int h = 0; h < 2; h++) {                                       \
                int rloc = m0 + mi * 16 + q + h * 8;                            \
                int tr = trC[rloc];                                             \
                float r_s = 0.f, s_s = 0.f;                                     \
                _Pragma("unroll")                                               \
                for (int ni = 0; ni < 4; ni++) {                                \
                    _Pragma("unroll")                                           \
                    for (int p = 0; p < 2; p++) {                               \
                        float e = ex2f(acc[mi][ni][h * 2 + p]);                 \
                        r_s += e;                                               \
                        if (tcJ[ni * 2 + p] == tr) s_s += e;                    \
                        if (DODIAG && (n0 + ni * 8 + t4 * 2 + p == rloc))       \
                            atomicAdd(&g_DS[tr], (double)e);                    \
                        if (DOCS) cs[ni][p] += e;                               \
                    }                                                           \
                }                                                               \
                r_s += __shfl_xor_sync(0xffffffffu, r_s, 1);                    \
                r_s += __shfl_xor_sync(0xffffffffu, r_s, 2);                    \
                s_s += __shfl_xor_sync(0xffffffffu, s_s, 1);                    \
                s_s += __shfl_xor_sync(0xffffffffu, s_s, 2);                    \
                if (t4 == 0) {                                                  \
                    rsS[slice * 128 + rloc] += r_s;                             \
                    ssS[slice * 128 + rloc] += s_s * (GM);                      \
                }                                                               \
            }                                                                   \
        }                                                                       \
        if (DOCS) {                                                             \
            _Pragma("unroll")                                                   \
            for (int ni = 0; ni < 4; ni++) {                                    \
                _Pragma("unroll")                                               \
                for (int p = 0; p < 2; p++) {                                   \
                    float v = cs[ni][p];                                        \
                    v += __shfl_xor_sync(0xffffffffu, v, 4);                    \
                    v += __shfl_xor_sync(0xffffffffu, v, 8);                    \
                    v += __shfl_xor_sync(0xffffffffu, v, 16);                   \
                    if (q == 0)                                                 \
                        atomicAdd(&g_RT[tcJ[ni * 2 + p]], (double)v);           \
                }                                                               \
            }                                                                   \
        }                                                                       \
    } while (0)

        if (isXY) {
            EPI_CORE(false, false, 1.f);
        } else if (isDiag) {
            EPI_CORE(true, false, 1.f);
        } else {
            EPI_CORE(false, true, 2.f);
        }
#undef EPI_CORE

        // ---- flush on strip/mode boundary ----
        bool nIsXY = haveNext && (un >= nXX - rn);
        bool keep = haveNext && (rn == rc) && (nIsXY == isXY);
        if (!keep) {
            __syncthreads();
            if (tid < 128) {
                float rv = rsS[tid] + rsS[128 + tid] + rsS[256 + tid] + rsS[384 + tid];
                float sv = ssS[tid] + ssS[128 + tid] + ssS[256 + tid] + ssS[384 + tid];
                int tr = trC[tid];
                if (isXY) {
                    atomicAdd(&g_A[tr], (double)rv);
                    atomicAdd(&g_P[tr], (double)sv);
                } else {
                    atomicAdd(&g_RT[tr], (double)rv);
                    atomicAdd(&g_G[tr], (double)sv);
                }
#pragma unroll
                for (int s = 0; s < 4; s++) {
                    rsS[s * 128 + tid] = 0.f;
                    ssS[s * 128 + tid] = 0.f;
                }
            }
        }

        rc = rn; uc = un;
        bBuf ^= 1;
        if (aFlip) aBuf ^= 1;
    }
#undef LOAD_A
#undef LOAD_B
}

// ---------------------------------------------------------------------------
__global__ void k_loss(float* out, int nQ) {
    __shared__ double warpsum[16];
    int n = g_n;
    int Q = nQ / n;
    double local = 0.0;
    for (int i = threadIdx.x; i < n; i += blockDim.x) {
        double num = g_P[i] + 0.5 * (g_G[i] - g_DS[i]);
        double den = (g_A[i] - g_P[i]) + (g_RT[i] - g_G[i]);
        local += (double)logf((float)((num + den) / num));
    }
#pragma unroll
    for (int o = 16; o >= 1; o >>= 1)
        local += __shfl_xor_sync(0xffffffffu, local, o);
    int lane = threadIdx.x & 31, wi = threadIdx.x >> 5;
    if (lane == 0) warpsum[wi] = local;
    __syncthreads();
    if (threadIdx.x == 0) {
        double t = 0.0;
        for (int i = 0; i < (int)(blockDim.x >> 5); i++) t += warpsum[i];
        out[0] = (float)(t / (double)n / (double)Q);
    }
}

// ---------------------------------------------------------------------------
extern "C" void kernel_launch(void* const* d_in, const int* in_sizes, int n_in,
                              void* d_out, int out_size) {
    const float* x   = (const float*)d_in[0];
    const int*   trk = (const int*)d_in[1];
    const float* y   = (const float*)d_in[2];
    float* out = (float*)d_out;

    int M  = in_sizes[1];
    int D  = in_sizes[0] / M;
    int nQ = in_sizes[2] / D;

    cudaFuncSetAttribute(k_gemm, cudaFuncAttributeMaxDynamicSharedMemorySize, SM_TOTAL);

    int prepThreads = (M * D + nQ * D) / 8;
    if (prepThreads < MAX_M) prepThreads = MAX_M;
    k_prep<<<(prepThreads + 255) / 256, 256>>>(x, y, trk, M, nQ);

    k_gemm<<<NPCTA, 256, SM_TOTAL>>>(trk, M, nQ);

    k_loss<<<1, 512>>>(out, nQ);
}

// round 12
// speedup vs baseline: 1.3602x; 1.0022x over previous
#include <cuda_runtime.h>
#include <math.h>
#include <stdint.h>

// ContrastiveLoss fused via warp-level FP8(e4m3) mma.sync (m16n8k32).
// Strip-major persistent CTAs, A resident per strip (double-buffered),
// B double-buffered, smem-staged row sums flushed at strip/mode boundaries,
// incremental tile tracking, mode-specialized epilogues, in-kernel loss tail.
// Inputs: x [M,D] f32, track_idxs [M] i32, y [n,Q,D] f32. Output: scalar f32.

#define MAX_M  8192
#define DK     128
#define TILE   128
#define ASTRB  144            // padded row stride in bytes
#define NPCTA  296            // 2 per SM

// smem layout (bytes)
#define GA0    0              // A buf0 128x144
#define GA1    18432          // A buf1
#define GB0    36864          // B buf0
#define GB1    55296          // B buf1
#define GTRS   73728          // 2 x 512 row labels (paired with A bufs)
#define GTCS   74752          // 2 x 512 col labels (paired with B bufs)
#define GRS    75776          // 4 slices x 128 f32 row sums
#define GSS    77824          // 4 slices x 128 f32 same-track sums
#define SM_TOTAL 79872

__device__ uint8_t g_xa[(size_t)MAX_M * DK];       // x * log2(e)/T, e4m3 (A)
__device__ uint8_t g_x8[(size_t)MAX_M * DK];       // x, e4m3 (B, xx)
__device__ uint8_t g_y8[(size_t)MAX_M * DK / 2];   // y, e4m3 (B, xy)
__device__ double g_A[MAX_M];
__device__ double g_P[MAX_M];
__device__ double g_RT[MAX_M];
__device__ double g_G[MAX_M];
__device__ double g_DS[MAX_M];
__device__ int    g_n = 0;
__device__ int    g_done = 0;

__device__ __forceinline__ uint32_t smem_u32(const void* p) {
    uint32_t a;
    asm("{ .reg .u64 t; cvta.to.shared.u64 t, %1; cvt.u32.u64 %0, t; }" : "=r"(a) : "l"(p));
    return a;
}
__device__ __forceinline__ float ex2f(float x) {
    float r; asm("ex2.approx.f32 %0, %1;" : "=f"(r) : "f"(x)); return r;
}
__device__ __forceinline__ void ldmx4(uint32_t* r, uint32_t addr) {
    asm volatile("ldmatrix.sync.aligned.m8n8.x4.shared.b16 {%0,%1,%2,%3}, [%4];"
                 : "=r"(r[0]), "=r"(r[1]), "=r"(r[2]), "=r"(r[3]) : "r"(addr));
}
__device__ __forceinline__ void mma16832(float* d, const uint32_t* a, uint32_t b0, uint32_t b1) {
    asm volatile("mma.sync.aligned.m16n8k32.row.col.f32.e4m3.e4m3.f32 "
                 "{%0,%1,%2,%3}, {%4,%5,%6,%7}, {%8,%9}, {%0,%1,%2,%3};"
                 : "+f"(d[0]), "+f"(d[1]), "+f"(d[2]), "+f"(d[3])
                 : "r"(a[0]), "r"(a[1]), "r"(a[2]), "r"(a[3]), "r"(b0), "r"(b1));
}
__device__ __forceinline__ void cpasync16(uint32_t saddr, const void* gptr) {
    asm volatile("cp.async.cg.shared.global [%0], [%1], 16;" :: "r"(saddr), "l"(gptr));
}
__device__ __forceinline__ uint32_t pack_e4m3_4(float a, float b, float c, float d) {
    uint16_t lo, hi;
    asm("cvt.rn.satfinite.e4m3x2.f32 %0, %1, %2;" : "=h"(lo) : "f"(b), "f"(a));
    asm("cvt.rn.satfinite.e4m3x2.f32 %0, %1, %2;" : "=h"(hi) : "f"(d), "f"(c));
    return (uint32_t)lo | ((uint32_t)hi << 16);
}

// ---------------------------------------------------------------------------
__global__ void k_prep(const float* __restrict__ x, const float* __restrict__ y,
                       const int* __restrict__ trk, int M, int nQ) {
    const float S = 1.4426950408889634f / 0.3f;   // log2(e)/TEMP
    int t = blockIdx.x * blockDim.x + threadIdx.x;
    int nx4 = M * DK / 4;
    int ny4 = nQ * DK / 4;
    if (t < nx4) {
        float4 v = *reinterpret_cast<const float4*>(x + t * 4);
        *reinterpret_cast<uint32_t*>(g_xa + t * 4) =
            pack_e4m3_4(v.x * S, v.y * S, v.z * S, v.w * S);
        *reinterpret_cast<uint32_t*>(g_x8 + t * 4) = pack_e4m3_4(v.x, v.y, v.z, v.w);
    } else if (t < nx4 + ny4) {
        int i = t - nx4;
        float4 v = *reinterpret_cast<const float4*>(y + i * 4);
        *reinterpret_cast<uint32_t*>(g_y8 + i * 4) = pack_e4m3_4(v.x, v.y, v.z, v.w);
    }
    if (t < MAX_M) { g_A[t] = 0; g_P[t] = 0; g_RT[t] = 0; g_G[t] = 0; g_DS[t] = 0; }
    if (t == 0) g_done = 0;
    if (t < M) atomicMax(&g_n, trk[t] + 1);
}

// ---------------------------------------------------------------------------
// strip-major unranking (used once per CTA). Strip r: xx col-blocks u=0..
// nXX-r-1 (u==0 diag), then nYc xy blocks. cum(r) = C*r - r(r-1)/2.
__device__ __forceinline__ void decode_t(int t, int C, int nXX, int& r, int& u) {
    float b = 2.f * C + 1.f;
    float disc = b * b - 8.f * (float)t;
    int rr = (int)((b - sqrtf(disc)) * 0.5f);
    if (rr < 0) rr = 0;
    if (rr > nXX - 1) rr = nXX - 1;
    while (rr + 1 <= nXX - 1 && (rr + 1) * C - ((rr + 1) * rr) / 2 <= t) rr++;
    while (rr > 0 && rr * C - (rr * (rr - 1)) / 2 > t) rr--;
    r = rr;
    u = t - (rr * C - (rr * (rr - 1)) / 2);
}

__global__ void __launch_bounds__(256, 2)
k_gemm(const int* __restrict__ trk, int M, int nQ, float* __restrict__ out) {
    extern __shared__ char smem[];
    uint32_t gb = smem_u32(smem);
    int tid = threadIdx.x;
    int w = tid >> 5, lane = tid & 31;
    int n = g_n;

    int nXX = M / TILE;           // 64
    int nYc = nQ / TILE;          // 32
    int C = nXX + nYc;            // 96
    int totTiles = nXX * C - (nXX * (nXX - 1)) / 2;   // 4128
    int start = (int)(((long long)blockIdx.x * totTiles) / gridDim.x);
    int end   = (int)(((long long)(blockIdx.x + 1) * totTiles) / gridDim.x);

    float* rsS = (float*)(smem + GRS);   // [4][128]
    float* ssS = (float*)(smem + GSS);   // [4][128]
    if (tid < 128) {
#pragma unroll
        for (int s = 0; s < 4; s++) { rsS[s * 128 + tid] = 0.f; ssS[s * 128 + tid] = 0.f; }
    }

    int m0 = (w >> 2) * 64;
    int n0 = (w & 3) * 32;
    int slice = w & 3;
    int lrow = lane & 15;
    int lhalf = (lane >> 4) * 16;
    int q = lane >> 2, t4 = lane & 3;

#define LOAD_A(RR, AB) do {                                                     \
        uint32_t dstA_ = gb + ((AB) ? GA1 : GA0);                               \
        const uint8_t* asrc_ = g_xa + (size_t)(RR) * TILE * DK;                 \
        _Pragma("unroll")                                                       \
        for (int it = 0; it < 4; it++) {                                        \
            int c_ = tid + it * 256;                                            \
            int row_ = c_ >> 3, col_ = (c_ & 7) << 4;                           \
            cpasync16(dstA_ + row_ * ASTRB + col_, asrc_ + row_ * DK + col_);   \
        }                                                                       \
        if (tid < 32)                                                           \
            cpasync16(gb + GTRS + (AB) * 512 + tid * 16,                        \
                      trk + (RR) * TILE + tid * 4);                             \
    } while (0)

#define LOAD_B(RR, UU, BB) do {                                                 \
        uint32_t dstB_ = gb + ((BB) ? GB1 : GB0);                               \
        int nxx_ = nXX - (RR);                                                  \
        if ((UU) < nxx_) {                                                      \
            int cblk_ = (RR) + (UU);                                            \
            const uint8_t* bsrc_ = g_x8 + (size_t)cblk_ * TILE * DK;            \
            _Pragma("unroll")                                                   \
            for (int it = 0; it < 4; it++) {                                    \
                int c_ = tid + it * 256;                                        \
                int row_ = c_ >> 3, col_ = (c_ & 7) << 4;                       \
                cpasync16(dstB_ + row_ * ASTRB + col_, bsrc_ + row_ * DK + col_);\
            }                                                                   \
            if (tid < 32)                                                       \
                cpasync16(gb + GTCS + (BB) * 512 + tid * 16,                    \
                          trk + cblk_ * TILE + tid * 4);                        \
        } else {                                                                \
            int j_ = (UU) - nxx_;                                               \
            const uint8_t* bsrc_ = g_y8 + (size_t)j_ * TILE * DK;               \
            _Pragma("unroll")                                                   \
            for (int it = 0; it < 4; it++) {                                    \
                int c_ = tid + it * 256;                                        \
                int row_ = c_ >> 3, col_ = (c_ & 7) << 4;                       \
                cpasync16(dstB_ + row_ * ASTRB + col_, bsrc_ + row_ * DK + col_);\
            }                                                                   \
            if (tid < 128)                                                      \
                ((int*)(smem + GTCS + (BB) * 512))[tid] = (j_ * TILE + tid) % n;\
        }                                                                       \
    } while (0)

    // ---- prologue ----
    int rc, uc;
    decode_t(start, C, nXX, rc, uc);
    int aBuf = 0, bBuf = 0;
    LOAD_A(rc, 0);
    LOAD_B(rc, uc, 0);
    asm volatile("cp.async.commit_group;" ::: "memory");

    for (int t = start; t < end; t++) {
        asm volatile("cp.async.wait_group 0;" ::: "memory");
        __syncthreads();

        // ---- next tile coords (incremental) ----
        bool haveNext = (t + 1 < end);
        int rn = rc, un = uc + 1;
        if (un == (nXX - rc) + nYc) { rn = rc + 1; un = 0; }
        bool aFlip = false;
        if (haveNext) {
            LOAD_B(rn, un, bBuf ^ 1);
            if (rn != rc) { LOAD_A(rn, aBuf ^ 1); aFlip = true; }
        }
        asm volatile("cp.async.commit_group;" ::: "memory");

        // ---- current tile flags ----
        bool isXY = (uc >= nXX - rc);
        bool isDiag = (uc == 0);
        const int* trC = (const int*)(smem + GTRS + aBuf * 512);
        const int* tcC = (const int*)(smem + GTCS + bBuf * 512);
        uint32_t aBase = gb + (aBuf ? GA1 : GA0);
        uint32_t bBase = gb + (bBuf ? GB1 : GB0);

        // ---- MMA ----
        uint32_t aAddr[4];
#pragma unroll
        for (int mi = 0; mi < 4; mi++)
            aAddr[mi] = aBase + (m0 + mi * 16 + lrow) * ASTRB + lhalf;
        uint32_t bAddr[2];
#pragma unroll
        for (int g2 = 0; g2 < 2; g2++)
            bAddr[g2] = bBase + (n0 + g2 * 16 + lrow) * ASTRB + lhalf;

        float acc[4][4][4];
#pragma unroll
        for (int mi = 0; mi < 4; mi++)
#pragma unroll
            for (int ni = 0; ni < 4; ni++)
#pragma unroll
                for (int e = 0; e < 4; e++) acc[mi][ni][e] = 0.f;

#pragma unroll
        for (int ks = 0; ks < 4; ks++) {
            uint32_t a[4][4], b[2][4];
#pragma unroll
            for (int mi = 0; mi < 4; mi++) ldmx4(a[mi], aAddr[mi] + ks * 32);
#pragma unroll
            for (int g2 = 0; g2 < 2; g2++) ldmx4(b[g2], bAddr[g2] + ks * 32);
#pragma unroll
            for (int mi = 0; mi < 4; mi++) {
                mma16832(acc[mi][0], a[mi], b[0][0], b[0][2]);
                mma16832(acc[mi][1], a[mi], b[0][1], b[0][3]);
                mma16832(acc[mi][2], a[mi], b[1][0], b[1][2]);
                mma16832(acc[mi][3], a[mi], b[1][1], b[1][3]);
            }
        }

        // ---- epilogue, specialized by tile mode ----
        int tcJ[8];
#pragma unroll
        for (int j = 0; j < 8; j++) {
            int ni = j >> 1, p = j & 1;
            tcJ[j] = tcC[n0 + ni * 8 + t4 * 2 + p];
        }

#define EPI_CORE(DODIAG, DOCS, GM) do {                                         \
        float cs[4][2] = {{0.f,0.f},{0.f,0.f},{0.f,0.f},{0.f,0.f}};             \
        _Pragma("unroll")                                                       \
        for (int mi = 0; mi < 4; mi++) {                                        \
            _Pragma("unroll")                                                   \
            for (int h = 0; h < 2; h++) {                                       \
                int rloc = m0 + mi * 16 + q + h * 8;                            \
                int tr = trC[rloc];                                             \
                float r_s = 0.f, s_s = 0.f;                                     \
                _Pragma("unroll")                                               \
                for (int ni = 0; ni < 4; ni++) {                                \
                    _Pragma("unroll")                                           \
                    for (int p = 0; p < 2; p++) {                               \
                        float e = ex2f(acc[mi][ni][h * 2 + p]);                 \
                        r_s += e;                                               \
                        if (tcJ[ni * 2 + p] == tr) s_s += e;                    \
                        if (DODIAG && (n0 + ni * 8 + t4 * 2 + p == rloc))       \
                            atomicAdd(&g_DS[tr], (double)e);                    \
                        if (DOCS) cs[ni][p] += e;                               \
                    }                                                           \
                }                                                               \
                r_s += __shfl_xor_sync(0xffffffffu, r_s, 1);                    \
                r_s += __shfl_xor_sync(0xffffffffu, r_s, 2);                    \
                s_s += __shfl_xor_sync(0xffffffffu, s_s, 1);                    \
                s_s += __shfl_xor_sync(0xffffffffu, s_s, 2);                    \
                if (t4 == 0) {                                                  \
                    rsS[slice * 128 + rloc] += r_s;                             \
                    ssS[slice * 128 + rloc] += s_s * (GM);                      \
                }                                                               \
            }                                                                   \
        }                                                                       \
        if (DOCS) {                                                             \
            _Pragma("unroll")                                                   \
            for (int ni = 0; ni < 4; ni++) {                                    \
                _Pragma("unroll")                                               \
                for (int p = 0; p < 2; p++) {                                   \
                    float v = cs[ni][p];                                        \
                    v += __shfl_xor_sync(0xffffffffu, v, 4);                    \
                    v += __shfl_xor_sync(0xffffffffu, v, 8);                    \
                    v += __shfl_xor_sync(0xffffffffu, v, 16);                   \
                    if (q == 0)                                                 \
                        atomicAdd(&g_RT[tcJ[ni * 2 + p]], (double)v);           \
                }                                                               \
            }                                                                   \
        }                                                                       \
    } while (0)

        if (isXY) {
            EPI_CORE(false, false, 1.f);
        } else if (isDiag) {
            EPI_CORE(true, false, 1.f);
        } else {
            EPI_CORE(false, true, 2.f);
        }
#undef EPI_CORE

        // ---- flush on strip/mode boundary ----
        bool nIsXY = haveNext && (un >= nXX - rn);
        bool keep = haveNext && (rn == rc) && (nIsXY == isXY);
        if (!keep) {
            __syncthreads();
            if (tid < 128) {
                float rv = rsS[tid] + rsS[128 + tid] + rsS[256 + tid] + rsS[384 + tid];
                float sv = ssS[tid] + ssS[128 + tid] + ssS[256 + tid] + ssS[384 + tid];
                int tr = trC[tid];
                if (isXY) {
                    atomicAdd(&g_A[tr], (double)rv);
                    atomicAdd(&g_P[tr], (double)sv);
                } else {
                    atomicAdd(&g_RT[tr], (double)rv);
                    atomicAdd(&g_G[tr], (double)sv);
                }
#pragma unroll
                for (int s = 0; s < 4; s++) {
                    rsS[s * 128 + tid] = 0.f;
                    ssS[s * 128 + tid] = 0.f;
                }
            }
        }

        rc = rn; uc = un;
        bBuf ^= 1;
        if (aFlip) aBuf ^= 1;
    }
#undef LOAD_A
#undef LOAD_B

    // ---- in-kernel loss: last CTA to finish computes the scalar ----
    __syncthreads();
    __threadfence();
    __shared__ int sTicket;
    if (tid == 0) sTicket = atomicAdd(&g_done, 1);
    __syncthreads();
    if (sTicket == (int)gridDim.x - 1) {
        __shared__ double warpsum[8];
        int Q = nQ / n;
        double local = 0.0;
        for (int i = tid; i < n; i += 256) {
            double num = g_P[i] + 0.5 * (g_G[i] - g_DS[i]);
            double den = (g_A[i] - g_P[i]) + (g_RT[i] - g_G[i]);
            local += (double)logf((float)((num + den) / num));
        }
#pragma unroll
        for (int o = 16; o >= 1; o >>= 1)
            local += __shfl_xor_sync(0xffffffffu, local, o);
        if (lane == 0) warpsum[w] = local;
        __syncthreads();
        if (tid == 0) {
            double tt = 0.0;
            for (int i = 0; i < 8; i++) tt += warpsum[i];
            out[0] = (float)(tt / (double)n / (double)Q);
        }
    }
}

// ---------------------------------------------------------------------------
extern "C" void kernel_launch(void* const* d_in, const int* in_sizes, int n_in,
                              void* d_out, int out_size) {
    const float* x   = (const float*)d_in[0];
    const int*   trk = (const int*)d_in[1];
    const float* y   = (const float*)d_in[2];
    float* out = (float*)d_out;

    int M  = in_sizes[1];
    int D  = in_sizes[0] / M;
    int nQ = in_sizes[2] / D;

    cudaFuncSetAttribute(k_gemm, cudaFuncAttributeMaxDynamicSharedMemorySize, SM_TOTAL);

    int prepThreads = (M * D + nQ * D) / 4;
    if (prepThreads < MAX_M) prepThreads = MAX_M;
    k_prep<<<(prepThreads + 255) / 256, 256>>>(x, y, trk, M, nQ);

    k_gemm<<<NPCTA, 256, SM_TOTAL>>>(trk, M, nQ, out);
}

// round 13
// speedup vs baseline: 1.3813x; 1.0155x over previous
#include <cuda_runtime.h>
#include <math.h>
#include <stdint.h>

// ContrastiveLoss fused via warp-level FP8(e4m3) mma.sync (m16n8k32).
// Strip-major persistent CTAs, A resident per strip (double-buffered),
// B double-buffered, smem-staged row sums flushed at strip/mode boundaries,
// incremental tile tracking, mode-specialized epilogues with warp-level
// no-match skip (label range test), in-kernel loss tail.
// Inputs: x [M,D] f32, track_idxs [M] i32, y [n,Q,D] f32. Output: scalar f32.

#define MAX_M  8192
#define DK     128
#define TILE   128
#define ASTRB  144            // padded row stride in bytes
#define NPCTA  296            // 2 per SM

// smem layout (bytes)
#define GA0    0              // A buf0 128x144
#define GA1    18432          // A buf1
#define GB0    36864          // B buf0
#define GB1    55296          // B buf1
#define GTRS   73728          // 2 x 512 row labels (paired with A bufs)
#define GTCS   74752          // 2 x 512 col labels (paired with B bufs)
#define GRS    75776          // 4 slices x 128 f32 row sums
#define GSS    77824          // 4 slices x 128 f32 same-track sums
#define SM_TOTAL 79872

__device__ uint8_t g_xa[(size_t)MAX_M * DK];       // x * log2(e)/T, e4m3 (A)
__device__ uint8_t g_x8[(size_t)MAX_M * DK];       // x, e4m3 (B, xx)
__device__ uint8_t g_y8[(size_t)MAX_M * DK / 2];   // y, e4m3 (B, xy)
__device__ double g_A[MAX_M];
__device__ double g_P[MAX_M];
__device__ double g_RT[MAX_M];
__device__ double g_G[MAX_M];
__device__ double g_DS[MAX_M];
__device__ int    g_n = 0;
__device__ int    g_done = 0;

__device__ __forceinline__ uint32_t smem_u32(const void* p) {
    uint32_t a;
    asm("{ .reg .u64 t; cvta.to.shared.u64 t, %1; cvt.u32.u64 %0, t; }" : "=r"(a) : "l"(p));
    return a;
}
__device__ __forceinline__ float ex2f(float x) {
    float r; asm("ex2.approx.f32 %0, %1;" : "=f"(r) : "f"(x)); return r;
}
__device__ __forceinline__ void ldmx4(uint32_t* r, uint32_t addr) {
    asm volatile("ldmatrix.sync.aligned.m8n8.x4.shared.b16 {%0,%1,%2,%3}, [%4];"
                 : "=r"(r[0]), "=r"(r[1]), "=r"(r[2]), "=r"(r[3]) : "r"(addr));
}
__device__ __forceinline__ void mma16832(float* d, const uint32_t* a, uint32_t b0, uint32_t b1) {
    asm volatile("mma.sync.aligned.m16n8k32.row.col.f32.e4m3.e4m3.f32 "
                 "{%0,%1,%2,%3}, {%4,%5,%6,%7}, {%8,%9}, {%0,%1,%2,%3};"
                 : "+f"(d[0]), "+f"(d[1]), "+f"(d[2]), "+f"(d[3])
                 : "r"(a[0]), "r"(a[1]), "r"(a[2]), "r"(a[3]), "r"(b0), "r"(b1));
}
__device__ __forceinline__ void cpasync16(uint32_t saddr, const void* gptr) {
    asm volatile("cp.async.cg.shared.global [%0], [%1], 16;" :: "r"(saddr), "l"(gptr));
}
__device__ __forceinline__ uint32_t pack_e4m3_4(float a, float b, float c, float d) {
    uint16_t lo, hi;
    asm("cvt.rn.satfinite.e4m3x2.f32 %0, %1, %2;" : "=h"(lo) : "f"(b), "f"(a));
    asm("cvt.rn.satfinite.e4m3x2.f32 %0, %1, %2;" : "=h"(hi) : "f"(d), "f"(c));
    return (uint32_t)lo | ((uint32_t)hi << 16);
}

// ---------------------------------------------------------------------------
__global__ void k_prep(const float* __restrict__ x, const float* __restrict__ y,
                       const int* __restrict__ trk, int M, int nQ) {
    const float S = 1.4426950408889634f / 0.3f;   // log2(e)/TEMP
    int t = blockIdx.x * blockDim.x + threadIdx.x;
    int nx4 = M * DK / 4;
    int ny4 = nQ * DK / 4;
    if (t < nx4) {
        float4 v = *reinterpret_cast<const float4*>(x + t * 4);
        *reinterpret_cast<uint32_t*>(g_xa + t * 4) =
            pack_e4m3_4(v.x * S, v.y * S, v.z * S, v.w * S);
        *reinterpret_cast<uint32_t*>(g_x8 + t * 4) = pack_e4m3_4(v.x, v.y, v.z, v.w);
    } else if (t < nx4 + ny4) {
        int i = t - nx4;
        float4 v = *reinterpret_cast<const float4*>(y + i * 4);
        *reinterpret_cast<uint32_t*>(g_y8 + i * 4) = pack_e4m3_4(v.x, v.y, v.z, v.w);
    }
    if (t < MAX_M) { g_A[t] = 0; g_P[t] = 0; g_RT[t] = 0; g_G[t] = 0; g_DS[t] = 0; }
    if (t == 0) g_done = 0;
    if (t < M) atomicMax(&g_n, trk[t] + 1);
}

// ---------------------------------------------------------------------------
// strip-major unranking (used once per CTA). Strip r: xx col-blocks u=0..
// nXX-r-1 (u==0 diag), then nYc xy blocks. cum(r) = C*r - r(r-1)/2.
__device__ __forceinline__ void decode_t(int t, int C, int nXX, int& r, int& u) {
    float b = 2.f * C + 1.f;
    float disc = b * b - 8.f * (float)t;
    int rr = (int)((b - sqrtf(disc)) * 0.5f);
    if (rr < 0) rr = 0;
    if (rr > nXX - 1) rr = nXX - 1;
    while (rr + 1 <= nXX - 1 && (rr + 1) * C - ((rr + 1) * rr) / 2 <= t) rr++;
    while (rr > 0 && rr * C - (rr * (rr - 1)) / 2 > t) rr--;
    r = rr;
    u = t - (rr * C - (rr * (rr - 1)) / 2);
}

__global__ void __launch_bounds__(256, 2)
k_gemm(const int* __restrict__ trk, int M, int nQ, float* __restrict__ out) {
    extern __shared__ char smem[];
    uint32_t gb = smem_u32(smem);
    int tid = threadIdx.x;
    int w = tid >> 5, lane = tid & 31;
    int n = g_n;

    int nXX = M / TILE;           // 64
    int nYc = nQ / TILE;          // 32
    int C = nXX + nYc;            // 96
    int totTiles = nXX * C - (nXX * (nXX - 1)) / 2;   // 4128
    int start = (int)(((long long)blockIdx.x * totTiles) / gridDim.x);
    int end   = (int)(((long long)(blockIdx.x + 1) * totTiles) / gridDim.x);

    float* rsS = (float*)(smem + GRS);   // [4][128]
    float* ssS = (float*)(smem + GSS);   // [4][128]
    if (tid < 128) {
#pragma unroll
        for (int s = 0; s < 4; s++) { rsS[s * 128 + tid] = 0.f; ssS[s * 128 + tid] = 0.f; }
    }

    int m0 = (w >> 2) * 64;
    int n0 = (w & 3) * 32;
    int slice = w & 3;
    int lrow = lane & 15;
    int lhalf = (lane >> 4) * 16;
    int q = lane >> 2, t4 = lane & 3;

#define LOAD_A(RR, AB) do {                                                     \
        uint32_t dstA_ = gb + ((AB) ? GA1 : GA0);                               \
        const uint8_t* asrc_ = g_xa + (size_t)(RR) * TILE * DK;                 \
        _Pragma("unroll")                                                       \
        for (int it = 0; it < 4; it++) {                                        \
            int c_ = tid + it * 256;                                            \
            int row_ = c_ >> 3, col_ = (c_ & 7) << 4;                           \
            cpasync16(dstA_ + row_ * ASTRB + col_, asrc_ + row_ * DK + col_);   \
        }                                                                       \
        if (tid < 32)                                                           \
            cpasync16(gb + GTRS + (AB) * 512 + tid * 16,                        \
                      trk + (RR) * TILE + tid * 4);                             \
    } while (0)

#define LOAD_B(RR, UU, BB) do {                                                 \
        uint32_t dstB_ = gb + ((BB) ? GB1 : GB0);                               \
        int nxx_ = nXX - (RR);                                                  \
        if ((UU) < nxx_) {                                                      \
            int cblk_ = (RR) + (UU);                                            \
            const uint8_t* bsrc_ = g_x8 + (size_t)cblk_ * TILE * DK;            \
            _Pragma("unroll")                                                   \
            for (int it = 0; it < 4; it++) {                                    \
                int c_ = tid + it * 256;                                        \
                int row_ = c_ >> 3, col_ = (c_ & 7) << 4;                       \
                cpasync16(dstB_ + row_ * ASTRB + col_, bsrc_ + row_ * DK + col_);\
            }                                                                   \
            if (tid < 32)                                                       \
                cpasync16(gb + GTCS + (BB) * 512 + tid * 16,                    \
                          trk + cblk_ * TILE + tid * 4);                        \
        } else {                                                                \
            int j_ = (UU) - nxx_;                                               \
            const uint8_t* bsrc_ = g_y8 + (size_t)j_ * TILE * DK;               \
            _Pragma("unroll")                                                   \
            for (int it = 0; it < 4; it++) {                                    \
                int c_ = tid + it * 256;                                        \
                int row_ = c_ >> 3, col_ = (c_ & 7) << 4;                       \
                cpasync16(dstB_ + row_ * ASTRB + col_, bsrc_ + row_ * DK + col_);\
            }                                                                   \
            if (tid < 128)                                                      \
                ((int*)(smem + GTCS + (BB) * 512))[tid] = (j_ * TILE + tid) % n;\
        }                                                                       \
    } while (0)

    // ---- prologue ----
    int rc, uc;
    decode_t(start, C, nXX, rc, uc);
    int aBuf = 0, bBuf = 0;
    if (start < end) {
        LOAD_A(rc, 0);
        LOAD_B(rc, uc, 0);
    }
    asm volatile("cp.async.commit_group;" ::: "memory");

    for (int t = start; t < end; t++) {
        asm volatile("cp.async.wait_group 0;" ::: "memory");
        __syncthreads();

        // ---- next tile coords (incremental) ----
        bool haveNext = (t + 1 < end);
        int rn = rc, un = uc + 1;
        if (un == (nXX - rc) + nYc) { rn = rc + 1; un = 0; }
        bool aFlip = false;
        if (haveNext) {
            LOAD_B(rn, un, bBuf ^ 1);
            if (rn != rc) { LOAD_A(rn, aBuf ^ 1); aFlip = true; }
        }
        asm volatile("cp.async.commit_group;" ::: "memory");

        // ---- current tile flags ----
        bool isXY = (uc >= nXX - rc);
        bool isDiag = (uc == 0);
        const int* trC = (const int*)(smem + GTRS + aBuf * 512);
        const int* tcC = (const int*)(smem + GTCS + bBuf * 512);
        uint32_t aBase = gb + (aBuf ? GA1 : GA0);
        uint32_t bBase = gb + (bBuf ? GB1 : GB0);

        // ---- MMA ----
        uint32_t aAddr[4];
#pragma unroll
        for (int mi = 0; mi < 4; mi++)
            aAddr[mi] = aBase + (m0 + mi * 16 + lrow) * ASTRB + lhalf;
        uint32_t bAddr[2];
#pragma unroll
        for (int g2 = 0; g2 < 2; g2++)
            bAddr[g2] = bBase + (n0 + g2 * 16 + lrow) * ASTRB + lhalf;

        float acc[4][4][4];
#pragma unroll
        for (int mi = 0; mi < 4; mi++)
#pragma unroll
            for (int ni = 0; ni < 4; ni++)
#pragma unroll
                for (int e = 0; e < 4; e++) acc[mi][ni][e] = 0.f;

#pragma unroll
        for (int ks = 0; ks < 4; ks++) {
            uint32_t a[4][4], b[2][4];
#pragma unroll
            for (int mi = 0; mi < 4; mi++) ldmx4(a[mi], aAddr[mi] + ks * 32);
#pragma unroll
            for (int g2 = 0; g2 < 2; g2++) ldmx4(b[g2], bAddr[g2] + ks * 32);
#pragma unroll
            for (int mi = 0; mi < 4; mi++) {
                mma16832(acc[mi][0], a[mi], b[0][0], b[0][2]);
                mma16832(acc[mi][1], a[mi], b[0][1], b[0][3]);
                mma16832(acc[mi][2], a[mi], b[1][0], b[1][2]);
                mma16832(acc[mi][3], a[mi], b[1][1], b[1][3]);
            }
        }

        // ---- labels + warp-level no-match test ----
        int tcJ[8];
#pragma unroll
        for (int j = 0; j < 8; j++) {
            int ni = j >> 1, p = j & 1;
            tcJ[j] = tcC[n0 + ni * 8 + t4 * 2 + p];
        }
        int trv[8];
#pragma unroll
        for (int mi = 0; mi < 4; mi++) {
            trv[mi * 2]     = trC[m0 + mi * 16 + q];
            trv[mi * 2 + 1] = trC[m0 + mi * 16 + q + 8];
        }
        int cmin = tcJ[0], cmax = tcJ[0];
#pragma unroll
        for (int j = 1; j < 8; j++) { cmin = min(cmin, tcJ[j]); cmax = max(cmax, tcJ[j]); }
        int rmin = trv[0], rmax = trv[0];
#pragma unroll
        for (int j = 1; j < 8; j++) { rmin = min(rmin, trv[j]); rmax = max(rmax, trv[j]); }
        bool poss = __any_sync(0xffffffffu,
                               !(rmax < cmin || rmin > cmax));

        // ---- epilogue, specialized by tile mode + match possibility ----
#define EPI_CORE(DOS, DODIAG, DOCS, GM) do {                                    \
        float cs[4][2] = {{0.f,0.f},{0.f,0.f},{0.f,0.f},{0.f,0.f}};             \
        _Pragma("unroll")                                                       \
        for (int mi = 0; mi < 4; mi++) {                                        \
            _Pragma("unroll")                                                   \
            for (int h = 0; h < 2; h++) {                                       \
                int rloc = m0 + mi * 16 + q + h * 8;                            \
                int tr = trv[mi * 2 + h];                                       \
                float r_s = 0.f, s_s = 0.f;                                     \
                _Pragma("unroll")                                               \
                for (int ni = 0; ni < 4; ni++) {                                \
                    _Pragma("unroll")                                           \
                    for (int p = 0; p < 2; p++) {                               \
                        float e = ex2f(acc[mi][ni][h * 2 + p]);                 \
                        r_s += e;                                               \
                        if (DOS && tcJ[ni * 2 + p] == tr) s_s += e;             \
                        if (DODIAG && (n0 + ni * 8 + t4 * 2 + p == rloc))       \
                            atomicAdd(&g_DS[tr], (double)e);                    \
                        if (DOCS) cs[ni][p] += e;                               \
                    }                                                           \
                }                                                               \
                r_s += __shfl_xor_sync(0xffffffffu, r_s, 1);                    \
                r_s += __shfl_xor_sync(0xffffffffu, r_s, 2);                    \
                if (DOS) {                                                      \
                    s_s += __shfl_xor_sync(0xffffffffu, s_s, 1);                \
                    s_s += __shfl_xor_sync(0xffffffffu, s_s, 2);                \
                }                                                               \
                if (t4 == 0) {                                                  \
                    rsS[slice * 128 + rloc] += r_s;                             \
                    if (DOS) ssS[slice * 128 + rloc] += s_s * (GM);             \
                }                                                               \
            }                                                                   \
        }                                                                       \
        if (DOCS) {                                                             \
            _Pragma("unroll")                                                   \
            for (int ni = 0; ni < 4; ni++) {                                    \
                _Pragma("unroll")                                               \
                for (int p = 0; p < 2; p++) {                                   \
                    float v = cs[ni][p];                                        \
                    v += __shfl_xor_sync(0xffffffffu, v, 4);                    \
                    v += __shfl_xor_sync(0xffffffffu, v, 8);                    \
                    v += __shfl_xor_sync(0xffffffffu, v, 16);                   \
                    if (q == 0)                                                 \
                        atomicAdd(&g_RT[tcJ[ni * 2 + p]], (double)v);           \
                }                                                               \
            }                                                                   \
        }                                                                       \
    } while (0)

        if (isXY) {
            if (poss) EPI_CORE(true, false, false, 1.f);
            else      EPI_CORE(false, false, false, 1.f);
        } else if (isDiag) {
            EPI_CORE(true, true, false, 1.f);
        } else {
            if (poss) EPI_CORE(true, false, true, 2.f);
            else      EPI_CORE(false, false, true, 2.f);
        }
#undef EPI_CORE

        // ---- flush on strip/mode boundary ----
        bool nIsXY = haveNext && (un >= nXX - rn);
        bool keep = haveNext && (rn == rc) && (nIsXY == isXY);
        if (!keep) {
            __syncthreads();
            if (tid < 128) {
                float rv = rsS[tid] + rsS[128 + tid] + rsS[256 + tid] + rsS[384 + tid];
                float sv = ssS[tid] + ssS[128 + tid] + ssS[256 + tid] + ssS[384 + tid];
                int tr = trC[tid];
                if (isXY) {
                    atomicAdd(&g_A[tr], (double)rv);
                    atomicAdd(&g_P[tr], (double)sv);
                } else {
                    atomicAdd(&g_RT[tr], (double)rv);
                    atomicAdd(&g_G[tr], (double)sv);
                }
#pragma unroll
                for (int s = 0; s < 4; s++) {
                    rsS[s * 128 + tid] = 0.f;
                    ssS[s * 128 + tid] = 0.f;
                }
            }
        }

        rc = rn; uc = un;
        bBuf ^= 1;
        if (aFlip) aBuf ^= 1;
    }
#undef LOAD_A
#undef LOAD_B

    // ---- in-kernel loss: last CTA to finish computes the scalar ----
    __syncthreads();
    __threadfence();
    __shared__ int sTicket;
    if (tid == 0) sTicket = atomicAdd(&g_done, 1);
    __syncthreads();
    if (sTicket == (int)gridDim.x - 1) {
        __shared__ double warpsum[8];
        int Q = nQ / n;
        double local = 0.0;
        for (int i = tid; i < n; i += 256) {
            double num = g_P[i] + 0.5 * (g_G[i] - g_DS[i]);
            double den = (g_A[i] - g_P[i]) + (g_RT[i] - g_G[i]);
            local += (double)logf((float)((num + den) / num));
        }
#pragma unroll
        for (int o = 16; o >= 1; o >>= 1)
            local += __shfl_xor_sync(0xffffffffu, local, o);
        if (lane == 0) warpsum[w] = local;
        __syncthreads();
        if (tid == 0) {
            double tt = 0.0;
            for (int i = 0; i < 8; i++) tt += warpsum[i];
            out[0] = (float)(tt / (double)n / (double)Q);
        }
    }
}

// ---------------------------------------------------------------------------
extern "C" void kernel_launch(void* const* d_in, const int* in_sizes, int n_in,
                              void* d_out, int out_size) {
    const float* x   = (const float*)d_in[0];
    const int*   trk = (const int*)d_in[1];
    const float* y   = (const float*)d_in[2];
    float* out = (float*)d_out;

    int M  = in_sizes[1];
    int D  = in_sizes[0] / M;
    int nQ = in_sizes[2] / D;

    cudaFuncSetAttribute(k_gemm, cudaFuncAttributeMaxDynamicSharedMemorySize, SM_TOTAL);

    int prepThreads = (M * D + nQ * D) / 4;
    if (prepThreads < MAX_M) prepThreads = MAX_M;
    k_prep<<<(prepThreads + 255) / 256, 256>>>(x, y, trk, M, nQ);

    k_gemm<<<NPCTA, 256, SM_TOTAL>>>(trk, M, nQ, out);
}